// round 4
// baseline (speedup 1.0000x reference)
#include <cuda_runtime.h>
#include <cuda_bf16.h>
#include <cuda_fp8.h>
#include <cstdint>
#include <math.h>

#define N_ROWS 16384
#define F_DIM  128
#define H1_DIM 64
#define H2_DIM 32
#define OUT_DIM 2

#define TB      128                       // gram tile (square)
#define NB      (N_ROWS / TB)             // 128 tile-blocks
#define N_TILES (NB * (NB + 1) / 2)       // 8256
#define GRIDG   296                       // persistent grid = 2 CTAs x 148 SMs

#define TILE_BYTES (TB * 128)             // 16384
// dynamic smem: [A0 | B0 | A1 | B1]
#define SM_TOTAL (4 * TILE_BYTES)         // 65536

// ---------------- device scratch ----------------
__device__ uint32_t g_x8[N_ROWS * 32];     // 2 MB: rows of 128 e4m3 (32 u32)
__device__ float    g_neigh[N_ROWS * F_DIM];
__device__ int      g_deg[N_ROWS];
__device__ float    g_logits[N_ROWS * OUT_DIM];
__device__ double   g_sum[2];
__device__ double   g_sq[2];

__device__ __forceinline__ uint32_t smem_u32(const void* p) {
    uint32_t a;
    asm("{ .reg .u64 t; cvta.to.shared.u64 t, %1; cvt.u32.u64 %0, t; }" : "=r"(a) : "l"(p));
    return a;
}

// byte offset inside a [128 x 128B] tile with per-row XOR swizzle (16B lanes)
__device__ __forceinline__ uint32_t swz_off(int r, int c16) {
    return (uint32_t)(r * 128 + ((c16 ^ (r & 7)) << 4));
}

// triangular decode: linear tile t -> (ib, jb), jb >= ib
__device__ __forceinline__ void decode_tile(int t, int& ib, int& jb) {
    int u = N_TILES - 1 - t;
    int rb = (int)((sqrtf(8.0f * (float)u + 1.0f) - 1.0f) * 0.5f);
    while (rb * (rb + 1) / 2 > u) rb--;
    while ((rb + 1) * (rb + 2) / 2 <= u) rb++;
    ib = NB - 1 - rb;
    jb = NB - 1 - (u - rb * (rb + 1) / 2);
}

// issue cp.async for one tile's A (and B if !diag)
__device__ __forceinline__ void load_tile(uint32_t sa, uint32_t sb, int ib, int jb,
                                          bool diag, int tid) {
    const char* gA = reinterpret_cast<const char*>(g_x8 + (size_t)ib * TB * 32);
    const char* gB = reinterpret_cast<const char*>(g_x8 + (size_t)jb * TB * 32);
#pragma unroll
    for (int it = 0; it < 4; it++) {
        int idx = tid + it * 256;
        int r = idx >> 3, c16 = idx & 7;
        uint32_t so = swz_off(r, c16);
        asm volatile("cp.async.cg.shared.global [%0], [%1], 16;"
                     :: "r"(sa + so), "l"(gA + idx * 16));
        if (!diag)
            asm volatile("cp.async.cg.shared.global [%0], [%1], 16;"
                         :: "r"(sb + so), "l"(gB + idx * 16));
    }
}

// compute one 128x128 tile: fp8 mma + threshold + sparse edge accumulation
__device__ __forceinline__ void compute_tile(uint32_t sa, uint32_t sb_use, int ib, int jb,
                                             int wid, int lane, const float* __restrict__ x) {
    int m0 = (wid & 3) * 32;   // 4 warps along M
    int n0 = (wid >> 2) * 64;  // 2 warps along N

    float acc[2][8][4];
#pragma unroll
    for (int mi = 0; mi < 2; mi++)
#pragma unroll
        for (int nj = 0; nj < 8; nj++)
#pragma unroll
            for (int r = 0; r < 4; r++) acc[mi][nj][r] = 0.f;

    int q = lane >> 3, L = lane & 7;
    int rq = (q & 1) * 8 + L;
    int kq = q >> 1;

#pragma unroll
    for (int kk = 0; kk < 4; kk++) {           // 4 chunks of k=32 fp8
        int cbase = kk * 2 + kq;
        uint32_t a[2][4];
#pragma unroll
        for (int mi = 0; mi < 2; mi++) {
            uint32_t addr = sa + swz_off(m0 + mi * 16 + rq, cbase);
            asm volatile("ldmatrix.sync.aligned.m8n8.x4.shared.b16 {%0,%1,%2,%3}, [%4];"
                         : "=r"(a[mi][0]), "=r"(a[mi][1]), "=r"(a[mi][2]), "=r"(a[mi][3])
                         : "r"(addr));
        }
        uint32_t b[8][2];
#pragma unroll
        for (int nq4 = 0; nq4 < 4; nq4++) {
            uint32_t r0, r1, r2, r3;
            uint32_t addr = sb_use + swz_off(n0 + nq4 * 16 + rq, cbase);
            asm volatile("ldmatrix.sync.aligned.m8n8.x4.shared.b16 {%0,%1,%2,%3}, [%4];"
                         : "=r"(r0), "=r"(r1), "=r"(r2), "=r"(r3)
                         : "r"(addr));
            b[nq4 * 2 + 0][0] = r0; b[nq4 * 2 + 0][1] = r2;
            b[nq4 * 2 + 1][0] = r1; b[nq4 * 2 + 1][1] = r3;
        }
#pragma unroll
        for (int mi = 0; mi < 2; mi++)
#pragma unroll
            for (int nj = 0; nj < 8; nj++)
                asm volatile(
                    "mma.sync.aligned.m16n8k32.row.col.f32.e4m3.e4m3.f32 "
                    "{%0,%1,%2,%3}, {%4,%5,%6,%7}, {%8,%9}, {%0,%1,%2,%3};"
                    : "+f"(acc[mi][nj][0]), "+f"(acc[mi][nj][1]),
                      "+f"(acc[mi][nj][2]), "+f"(acc[mi][nj][3])
                    : "r"(a[mi][0]), "r"(a[mi][1]), "r"(a[mi][2]), "r"(a[mi][3]),
                      "r"(b[nj][0]), "r"(b[nj][1]));
    }

    // epilogue: screened threshold + (rare) symmetric edge accumulation
    int g = lane >> 2, tg = lane & 3;
#pragma unroll
    for (int mi = 0; mi < 2; mi++) {
#pragma unroll
        for (int nj = 0; nj < 8; nj++) {
            float c0 = acc[mi][nj][0], c1 = acc[mi][nj][1];
            float c2 = acc[mi][nj][2], c3 = acc[mi][nj][3];
            float m = fmaxf(fmaxf(fabsf(c0), fabsf(c1)), fmaxf(fabsf(c2), fabsf(c3)));
            if (__any_sync(0xffffffffu, m >= 0.9486f)) {
#pragma unroll
                for (int r = 0; r < 4; r++) {
                    float c = acc[mi][nj][r];
                    if (c * c >= 0.9f) {
                        int i = ib * TB + m0 + mi * 16 + g + (r >> 1) * 8;
                        int j = jb * TB + n0 + nj * 8 + 2 * tg + (r & 1);
                        if (i < j) {
                            atomicAdd(&g_deg[i], 1);
                            atomicAdd(&g_deg[j], 1);
                            const float* xi = x + (size_t)i * F_DIM;
                            const float* xj = x + (size_t)j * F_DIM;
                            float* ni = g_neigh + (size_t)i * F_DIM;
                            float* nj_ = g_neigh + (size_t)j * F_DIM;
                            for (int f = 0; f < F_DIM; f++) {
                                atomicAdd(&ni[f], xj[f]);
                                atomicAdd(&nj_[f], xi[f]);
                            }
                        }
                    }
                }
            }
        }
    }
}

// ---------------- kernel 1: row norms -> e4m3, zero scratch ----------------
__global__ void __launch_bounds__(256) k_norm(const float* __restrict__ x) {
    if (blockIdx.x == 0 && threadIdx.x == 0) {
        g_sum[0] = 0.0; g_sum[1] = 0.0; g_sq[0] = 0.0; g_sq[1] = 0.0;
    }
    int warp = (blockIdx.x * blockDim.x + threadIdx.x) >> 5;
    int lane = threadIdx.x & 31;
    if (warp >= N_ROWS) return;
    float4 v = reinterpret_cast<const float4*>(x)[(size_t)warp * 32 + lane];
    float s = v.x * v.x + v.y * v.y + v.z * v.z + v.w * v.w;
#pragma unroll
    for (int o = 16; o > 0; o >>= 1) s += __shfl_xor_sync(0xffffffffu, s, o);
    float inv = 1.0f / (sqrtf(s) + 1e-12f);
    __nv_fp8x2_storage_t p0 = __nv_cvt_float2_to_fp8x2(make_float2(v.x * inv, v.y * inv),
                                                       __NV_SATFINITE, __NV_E4M3);
    __nv_fp8x2_storage_t p1 = __nv_cvt_float2_to_fp8x2(make_float2(v.z * inv, v.w * inv),
                                                       __NV_SATFINITE, __NV_E4M3);
    g_x8[warp * 32 + lane] = (uint32_t)p0 | ((uint32_t)p1 << 16);
    reinterpret_cast<float4*>(g_neigh)[(size_t)warp * 32 + lane] = make_float4(0.f, 0.f, 0.f, 0.f);
    if (lane == 0) g_deg[warp] = 0;
}

// ---------------- kernel 2: persistent double-buffered fp8 gram ----------------
__global__ void __launch_bounds__(256, 2) k_gram(const float* __restrict__ x) {
    extern __shared__ char smem[];
    uint32_t sbase = smem_u32(smem);
    int tid = threadIdx.x;
    int wid = tid >> 5, lane = tid & 31;

    // prologue: load first tile into buffer 0
    int tcur = blockIdx.x;
    int ib, jb;
    decode_tile(tcur, ib, jb);
    bool diag = (ib == jb);
    load_tile(sbase, sbase + TILE_BYTES, ib, jb, diag, tid);
    asm volatile("cp.async.commit_group;");

    int parity = 0;
    while (tcur < N_TILES) {
        // prefetch next tile into the other buffer
        int tnext = tcur + GRIDG;
        int ib2 = 0, jb2 = 0;
        bool diag2 = false;
        if (tnext < N_TILES) {
            decode_tile(tnext, ib2, jb2);
            diag2 = (ib2 == jb2);
            uint32_t nb = sbase + (parity ^ 1) * 2 * TILE_BYTES;
            load_tile(nb, nb + TILE_BYTES, ib2, jb2, diag2, tid);
        }
        asm volatile("cp.async.commit_group;");
        // current tile's group is 1-deep behind the just-committed one
        asm volatile("cp.async.wait_group 1;");
        __syncthreads();

        uint32_t sa = sbase + parity * 2 * TILE_BYTES;
        uint32_t sb_use = diag ? sa : (sa + TILE_BYTES);
        compute_tile(sa, sb_use, ib, jb, wid, lane, x);
        __syncthreads();   // all warps done reading before this buffer is reloaded

        tcur = tnext; ib = ib2; jb = jb2; diag = diag2; parity ^= 1;
    }
}

// ---------------- kernel 3: aggregation + MLP + BN statistics ----------------
__global__ void __launch_bounds__(256) k_mlp(const float* __restrict__ x,
                                             const float* __restrict__ W1, const float* __restrict__ b1,
                                             const float* __restrict__ W2, const float* __restrict__ b2,
                                             const float* __restrict__ W3, const float* __restrict__ b3) {
    __shared__ float sW1[F_DIM * H1_DIM];
    __shared__ float sW2[H1_DIM * H2_DIM];
    __shared__ float sW3[H2_DIM * OUT_DIM];
    __shared__ float sb1[H1_DIM], sb2[H2_DIM], sb3[OUT_DIM];
    __shared__ double swarp[8 * 4];

    int tid = threadIdx.x;
    for (int i = tid; i < F_DIM * H1_DIM; i += 256) sW1[i] = W1[i];
    for (int i = tid; i < H1_DIM * H2_DIM; i += 256) sW2[i] = W2[i];
    if (tid < H2_DIM * OUT_DIM) sW3[tid] = W3[tid];
    if (tid < H1_DIM) sb1[tid] = b1[tid];
    if (tid < H2_DIM) sb2[tid] = b2[tid];
    if (tid < OUT_DIM) sb3[tid] = b3[tid];
    __syncthreads();

    int row = blockIdx.x * 256 + tid;
    const float* xr = x + (size_t)row * F_DIM;
    const float* nr = g_neigh + (size_t)row * F_DIM;
    int d = g_deg[row];
    float invd = d > 0 ? 1.0f / (float)d : 0.f;

    float h1[H1_DIM];
#pragma unroll
    for (int k = 0; k < H1_DIM; k++) h1[k] = sb1[k];
    for (int f = 0; f < F_DIM; f++) {
        float a = (d > 0) ? 0.5f * (xr[f] + nr[f] * invd) : xr[f];
#pragma unroll
        for (int k = 0; k < H1_DIM; k++) h1[k] += a * sW1[f * H1_DIM + k];
    }
    float h2[H2_DIM];
#pragma unroll
    for (int m = 0; m < H2_DIM; m++) h2[m] = sb2[m];
#pragma unroll
    for (int k = 0; k < H1_DIM; k++) {
        float hk = fmaxf(h1[k], 0.f);
#pragma unroll
        for (int m = 0; m < H2_DIM; m++) h2[m] += hk * sW2[k * H2_DIM + m];
    }
    float l0 = sb3[0], l1 = sb3[1];
#pragma unroll
    for (int m = 0; m < H2_DIM; m++) {
        float hm = fmaxf(h2[m], 0.f);
        l0 += hm * sW3[m * 2 + 0];
        l1 += hm * sW3[m * 2 + 1];
    }
    g_logits[row * 2 + 0] = l0;
    g_logits[row * 2 + 1] = l1;

    double v[4] = { (double)l0, (double)l1, (double)l0 * l0, (double)l1 * l1 };
    int lane = tid & 31, wid = tid >> 5;
#pragma unroll
    for (int s = 0; s < 4; s++) {
        double t = v[s];
#pragma unroll
        for (int o = 16; o > 0; o >>= 1) t += __shfl_xor_sync(0xffffffffu, t, o);
        if (lane == 0) swarp[wid * 4 + s] = t;
    }
    __syncthreads();
    if (tid < 4) {
        double s = 0.0;
#pragma unroll
        for (int w = 0; w < 8; w++) s += swarp[w * 4 + tid];
        if (tid < 2) atomicAdd(&g_sum[tid], s);
        else         atomicAdd(&g_sq[tid - 2], s);
    }
}

// ---------------- kernel 4: batch-norm normalize ----------------
__global__ void __launch_bounds__(256) k_bn(const float* __restrict__ gamma,
                                            const float* __restrict__ beta,
                                            float* __restrict__ out) {
    __shared__ float s_scale[2], s_shift[2];
    if (threadIdx.x < 2) {
        int c = threadIdx.x;
        double n = (double)N_ROWS;
        double mu = g_sum[c] / n;
        double var = g_sq[c] / n - mu * mu;
        double inv = 1.0 / sqrt(var + 1e-5);
        float g = gamma[c];
        s_scale[c] = (float)inv * g;
        s_shift[c] = beta[c] - (float)(mu * inv) * g;
    }
    __syncthreads();
    int idx = blockIdx.x * blockDim.x + threadIdx.x;
    if (idx >= N_ROWS * OUT_DIM) return;
    int c = idx & 1;
    out[idx] = g_logits[idx] * s_scale[c] + s_shift[c];
}

// ---------------- launch ----------------
extern "C" void kernel_launch(void* const* d_in, const int* in_sizes, int n_in,
                              void* d_out, int out_size) {
    const float* x     = (const float*)d_in[0];
    const float* W1    = (const float*)d_in[1];
    const float* b1    = (const float*)d_in[2];
    const float* W2    = (const float*)d_in[3];
    const float* b2    = (const float*)d_in[4];
    const float* W3    = (const float*)d_in[5];
    const float* b3    = (const float*)d_in[6];
    const float* gamma = (const float*)d_in[7];
    const float* beta  = (const float*)d_in[8];
    float* out = (float*)d_out;

    k_norm<<<N_ROWS / 8, 256>>>(x);

    cudaFuncSetAttribute(k_gram, cudaFuncAttributeMaxDynamicSharedMemorySize, SM_TOTAL);
    k_gram<<<GRIDG, 256, SM_TOTAL>>>(x);

    k_mlp<<<N_ROWS / 256, 256>>>(x, W1, b1, W2, b2, W3, b3);
    k_bn<<<(N_ROWS * OUT_DIM + 255) / 256, 256>>>(gamma, beta, out);
}

// round 5
// speedup vs baseline: 1.3348x; 1.3348x over previous
#include <cuda_runtime.h>
#include <cuda_bf16.h>
#include <cuda_fp8.h>
#include <cstdint>
#include <math.h>

#define N_ROWS 16384
#define F_DIM  128
#define KHEAD  64                         // head features on tensor cores
#define H1_DIM 64
#define H2_DIM 32
#define OUT_DIM 2

#define TB      128                       // gram tile (square)
#define NB      (N_ROWS / TB)             // 128
#define N_TILES (NB * (NB + 1) / 2)       // 8256

#define SCREEN_T 0.9186f                  // sqrt(0.9) - 0.03 fp8 margin

// ---------------- device scratch ----------------
__device__ uint32_t g_x8[N_ROWS * 16];     // 1 MB: head rows, 64 e4m3 = 16 u32
__device__ float    g_tail[N_ROWS];        // tail norm of normalized row
__device__ float    g_rnorm[N_ROWS];       // 1/(||x||+1e-12)
__device__ float    g_neigh[N_ROWS * F_DIM];
__device__ int      g_deg[N_ROWS];
__device__ float    g_logits[N_ROWS * OUT_DIM];
__device__ double   g_sum[2];
__device__ double   g_sq[2];

__device__ __forceinline__ uint32_t smem_u32(const void* p) {
    uint32_t a;
    asm("{ .reg .u64 t; cvta.to.shared.u64 t, %1; cvt.u32.u64 %0, t; }" : "=r"(a) : "l"(p));
    return a;
}

// pack two 64B logical rows per 128B smem row, XOR-swizzled 16B units.
// r: logical row 0..127, c: 16B chunk 0..3
__device__ __forceinline__ uint32_t pack_off(int r, int c) {
    int R = r >> 1;
    int u = ((r & 1) << 2) | c;
    return (uint32_t)(R * 128 + ((u ^ (R & 7)) << 4));
}

// triangular decode: linear tile t -> (ib, jb), jb >= ib
__device__ __forceinline__ void decode_tile(int t, int& ib, int& jb) {
    int u = N_TILES - 1 - t;
    int rb = (int)((sqrtf(8.0f * (float)u + 1.0f) - 1.0f) * 0.5f);
    while (rb * (rb + 1) / 2 > u) rb--;
    while ((rb + 1) * (rb + 2) / 2 <= u) rb++;
    ib = NB - 1 - rb;
    jb = NB - 1 - (u - rb * (rb + 1) / 2);
}

// ---------------- kernel 1: norms, head->e4m3, tail norms, zero scratch ----------------
__global__ void __launch_bounds__(256) k_norm(const float* __restrict__ x) {
    if (blockIdx.x == 0 && threadIdx.x == 0) {
        g_sum[0] = 0.0; g_sum[1] = 0.0; g_sq[0] = 0.0; g_sq[1] = 0.0;
    }
    int row = (blockIdx.x * blockDim.x + threadIdx.x) >> 5;
    int lane = threadIdx.x & 31;
    if (row >= N_ROWS) return;
    float4 v = reinterpret_cast<const float4*>(x)[(size_t)row * 32 + lane];
    float ss = v.x * v.x + v.y * v.y + v.z * v.z + v.w * v.w;
    float st = (lane >= 16) ? ss : 0.f;
#pragma unroll
    for (int o = 16; o > 0; o >>= 1) {
        ss += __shfl_xor_sync(0xffffffffu, ss, o);
        st += __shfl_xor_sync(0xffffffffu, st, o);
    }
    float inv = 1.0f / (sqrtf(ss) + 1e-12f);
    if (lane < 16) {   // head features -> fp8
        __nv_fp8x2_storage_t p0 = __nv_cvt_float2_to_fp8x2(make_float2(v.x * inv, v.y * inv),
                                                           __NV_SATFINITE, __NV_E4M3);
        __nv_fp8x2_storage_t p1 = __nv_cvt_float2_to_fp8x2(make_float2(v.z * inv, v.w * inv),
                                                           __NV_SATFINITE, __NV_E4M3);
        g_x8[row * 16 + lane] = (uint32_t)p0 | ((uint32_t)p1 << 16);
    }
    if (lane == 0) {
        g_tail[row] = sqrtf(st) * inv;
        g_rnorm[row] = inv;
        g_deg[row] = 0;
    }
    reinterpret_cast<float4*>(g_neigh)[(size_t)row * 32 + lane] = make_float4(0.f, 0.f, 0.f, 0.f);
}

// ---------------- kernel 2: fp8 head-gram + tail-bound screen + exact recheck ----------------
__global__ void __launch_bounds__(256, 2) k_gram(const float* __restrict__ x) {
    int ib, jb;
    decode_tile(blockIdx.x, ib, jb);
    bool diag = (ib == jb);

    __shared__ char sA[TB * 64];
    __shared__ char sB[TB * 64];
    __shared__ float stA[TB];
    __shared__ float stB[TB];

    int tid = threadIdx.x;
    uint32_t sa = smem_u32(sA), sbm = smem_u32(sB);
    uint32_t sta = smem_u32(stA), stb = smem_u32(stB);

    // head tiles: 512 x 16B chunks each; 2 per thread
    const char* gA = reinterpret_cast<const char*>(g_x8 + (size_t)ib * TB * 16);
    const char* gB = reinterpret_cast<const char*>(g_x8 + (size_t)jb * TB * 16);
#pragma unroll
    for (int it = 0; it < 2; it++) {
        int idx = tid + it * 256;
        int r = idx >> 2, c = idx & 3;
        uint32_t so = pack_off(r, c);
        asm volatile("cp.async.cg.shared.global [%0], [%1], 16;"
                     :: "r"(sa + so), "l"(gA + idx * 16));
        if (!diag)
            asm volatile("cp.async.cg.shared.global [%0], [%1], 16;"
                         :: "r"(sbm + so), "l"(gB + idx * 16));
    }
    // tail norms: 32 x 16B per side
    if (tid < 32) {
        asm volatile("cp.async.ca.shared.global [%0], [%1], 16;"
                     :: "r"(sta + tid * 16),
                        "l"(reinterpret_cast<const char*>(g_tail + ib * TB) + tid * 16));
    } else if (tid < 64) {
        int t = tid - 32;
        asm volatile("cp.async.ca.shared.global [%0], [%1], 16;"
                     :: "r"(stb + t * 16),
                        "l"(reinterpret_cast<const char*>(g_tail + jb * TB) + t * 16));
    }
    asm volatile("cp.async.commit_group;");
    asm volatile("cp.async.wait_group 0;");
    __syncthreads();

    uint32_t sb_use = diag ? sa : sbm;

    int wid = tid >> 5, lane = tid & 31;
    int m0 = (wid & 3) * 32;   // 4 warps along M
    int n0 = (wid >> 2) * 64;  // 2 warps along N

    float acc[2][8][4];
#pragma unroll
    for (int mi = 0; mi < 2; mi++)
#pragma unroll
        for (int nj = 0; nj < 8; nj++)
#pragma unroll
            for (int r = 0; r < 4; r++) acc[mi][nj][r] = 0.f;

    int q = lane >> 3, L = lane & 7;
    int rq = (q & 1) * 8 + L;
    int kq = q >> 1;

#pragma unroll
    for (int kk = 0; kk < 2; kk++) {           // 2 chunks of k=32 fp8 (head only)
        int cbase = kk * 2 + kq;
        uint32_t a[2][4];
#pragma unroll
        for (int mi = 0; mi < 2; mi++) {
            uint32_t addr = sa + pack_off(m0 + mi * 16 + rq, cbase);
            asm volatile("ldmatrix.sync.aligned.m8n8.x4.shared.b16 {%0,%1,%2,%3}, [%4];"
                         : "=r"(a[mi][0]), "=r"(a[mi][1]), "=r"(a[mi][2]), "=r"(a[mi][3])
                         : "r"(addr));
        }
        uint32_t b[8][2];
#pragma unroll
        for (int nq4 = 0; nq4 < 4; nq4++) {
            uint32_t r0, r1, r2, r3;
            uint32_t addr = sb_use + pack_off(n0 + nq4 * 16 + rq, cbase);
            asm volatile("ldmatrix.sync.aligned.m8n8.x4.shared.b16 {%0,%1,%2,%3}, [%4];"
                         : "=r"(r0), "=r"(r1), "=r"(r2), "=r"(r3)
                         : "r"(addr));
            b[nq4 * 2 + 0][0] = r0; b[nq4 * 2 + 0][1] = r2;
            b[nq4 * 2 + 1][0] = r1; b[nq4 * 2 + 1][1] = r3;
        }
#pragma unroll
        for (int mi = 0; mi < 2; mi++)
#pragma unroll
            for (int nj = 0; nj < 8; nj++)
                asm volatile(
                    "mma.sync.aligned.m16n8k32.row.col.f32.e4m3.e4m3.f32 "
                    "{%0,%1,%2,%3}, {%4,%5,%6,%7}, {%8,%9}, {%0,%1,%2,%3};"
                    : "+f"(acc[mi][nj][0]), "+f"(acc[mi][nj][1]),
                      "+f"(acc[mi][nj][2]), "+f"(acc[mi][nj][3])
                    : "r"(a[mi][0]), "r"(a[mi][1]), "r"(a[mi][2]), "r"(a[mi][3]),
                      "r"(b[nj][0]), "r"(b[nj][1]));
    }

    // epilogue: bound = |c_head| + ti*tj; screen; survivors -> exact fp32 check
    int g = lane >> 2, tg = lane & 3;
    float ti[2][2];
#pragma unroll
    for (int mi = 0; mi < 2; mi++)
#pragma unroll
        for (int h = 0; h < 2; h++)
            ti[mi][h] = stA[m0 + mi * 16 + g + h * 8];
    float tj0[8], tj1[8];
    const float* stB_use = diag ? stA : stB;
#pragma unroll
    for (int nj = 0; nj < 8; nj++) {
        int j = n0 + nj * 8 + 2 * tg;
        tj0[nj] = stB_use[j];
        tj1[nj] = stB_use[j + 1];
    }

#pragma unroll
    for (int mi = 0; mi < 2; mi++) {
#pragma unroll
        for (int nj = 0; nj < 8; nj++) {
            float bnd[4];
            bnd[0] = fabsf(acc[mi][nj][0]) + ti[mi][0] * tj0[nj];
            bnd[1] = fabsf(acc[mi][nj][1]) + ti[mi][0] * tj1[nj];
            bnd[2] = fabsf(acc[mi][nj][2]) + ti[mi][1] * tj0[nj];
            bnd[3] = fabsf(acc[mi][nj][3]) + ti[mi][1] * tj1[nj];
            float bm = fmaxf(fmaxf(bnd[0], bnd[1]), fmaxf(bnd[2], bnd[3]));
            if (__any_sync(0xffffffffu, bm >= SCREEN_T)) {
#pragma unroll
                for (int r = 0; r < 4; r++) {
                    if (bnd[r] >= SCREEN_T) {
                        int i = ib * TB + m0 + mi * 16 + g + (r >> 1) * 8;
                        int j = jb * TB + n0 + nj * 8 + 2 * tg + (r & 1);
                        if (i < j) {
                            // exact fp32 recheck
                            const float4* xi = reinterpret_cast<const float4*>(x) + (size_t)i * 32;
                            const float4* xj = reinterpret_cast<const float4*>(x) + (size_t)j * 32;
                            float cdot = 0.f;
                            for (int f = 0; f < 32; f++) {
                                float4 a4 = xi[f], b4 = xj[f];
                                cdot += a4.x * b4.x + a4.y * b4.y + a4.z * b4.z + a4.w * b4.w;
                            }
                            cdot *= g_rnorm[i] * g_rnorm[j];
                            if (cdot * cdot >= 0.9f) {
                                atomicAdd(&g_deg[i], 1);
                                atomicAdd(&g_deg[j], 1);
                                const float* xif = x + (size_t)i * F_DIM;
                                const float* xjf = x + (size_t)j * F_DIM;
                                float* ni = g_neigh + (size_t)i * F_DIM;
                                float* njp = g_neigh + (size_t)j * F_DIM;
                                for (int f = 0; f < F_DIM; f++) {
                                    atomicAdd(&ni[f], xjf[f]);
                                    atomicAdd(&njp[f], xif[f]);
                                }
                            }
                        }
                    }
                }
            }
        }
    }
}

// ---------------- kernel 3: aggregation + MLP + BN statistics ----------------
__global__ void __launch_bounds__(128) k_mlp(const float* __restrict__ x,
                                             const float* __restrict__ W1, const float* __restrict__ b1,
                                             const float* __restrict__ W2, const float* __restrict__ b2,
                                             const float* __restrict__ W3, const float* __restrict__ b3) {
    __shared__ float sW1[F_DIM * H1_DIM];
    __shared__ float sW2[H1_DIM * H2_DIM];
    __shared__ float sW3[H2_DIM * OUT_DIM];
    __shared__ float sb1[H1_DIM], sb2[H2_DIM], sb3[OUT_DIM];
    __shared__ double swarp[4 * 4];

    int tid = threadIdx.x;
    for (int i = tid; i < F_DIM * H1_DIM; i += 128) sW1[i] = W1[i];
    for (int i = tid; i < H1_DIM * H2_DIM; i += 128) sW2[i] = W2[i];
    if (tid < H2_DIM * OUT_DIM) sW3[tid] = W3[tid];
    if (tid < H1_DIM) sb1[tid] = b1[tid];
    if (tid < H2_DIM) sb2[tid] = b2[tid];
    if (tid < OUT_DIM) sb3[tid] = b3[tid];
    __syncthreads();

    int row = blockIdx.x * 128 + tid;
    const float* xr = x + (size_t)row * F_DIM;
    const float* nr = g_neigh + (size_t)row * F_DIM;
    int d = g_deg[row];
    float invd = d > 0 ? 1.0f / (float)d : 0.f;

    float h1[H1_DIM];
#pragma unroll
    for (int k = 0; k < H1_DIM; k++) h1[k] = sb1[k];
    for (int f = 0; f < F_DIM; f++) {
        float a = (d > 0) ? 0.5f * (xr[f] + nr[f] * invd) : xr[f];
#pragma unroll
        for (int k = 0; k < H1_DIM; k++) h1[k] += a * sW1[f * H1_DIM + k];
    }
    float h2[H2_DIM];
#pragma unroll
    for (int m = 0; m < H2_DIM; m++) h2[m] = sb2[m];
#pragma unroll
    for (int k = 0; k < H1_DIM; k++) {
        float hk = fmaxf(h1[k], 0.f);
#pragma unroll
        for (int m = 0; m < H2_DIM; m++) h2[m] += hk * sW2[k * H2_DIM + m];
    }
    float l0 = sb3[0], l1 = sb3[1];
#pragma unroll
    for (int m = 0; m < H2_DIM; m++) {
        float hm = fmaxf(h2[m], 0.f);
        l0 += hm * sW3[m * 2 + 0];
        l1 += hm * sW3[m * 2 + 1];
    }
    g_logits[row * 2 + 0] = l0;
    g_logits[row * 2 + 1] = l1;

    double v[4] = { (double)l0, (double)l1, (double)l0 * l0, (double)l1 * l1 };
    int lane = tid & 31, wid = tid >> 5;
#pragma unroll
    for (int s = 0; s < 4; s++) {
        double t = v[s];
#pragma unroll
        for (int o = 16; o > 0; o >>= 1) t += __shfl_xor_sync(0xffffffffu, t, o);
        if (lane == 0) swarp[wid * 4 + s] = t;
    }
    __syncthreads();
    if (tid < 4) {
        double s = 0.0;
#pragma unroll
        for (int w = 0; w < 4; w++) s += swarp[w * 4 + tid];
        if (tid < 2) atomicAdd(&g_sum[tid], s);
        else         atomicAdd(&g_sq[tid - 2], s);
    }
}

// ---------------- kernel 4: batch-norm normalize ----------------
__global__ void __launch_bounds__(256) k_bn(const float* __restrict__ gamma,
                                            const float* __restrict__ beta,
                                            float* __restrict__ out) {
    __shared__ float s_scale[2], s_shift[2];
    if (threadIdx.x < 2) {
        int c = threadIdx.x;
        double n = (double)N_ROWS;
        double mu = g_sum[c] / n;
        double var = g_sq[c] / n - mu * mu;
        double inv = 1.0 / sqrt(var + 1e-5);
        float g = gamma[c];
        s_scale[c] = (float)inv * g;
        s_shift[c] = beta[c] - (float)(mu * inv) * g;
    }
    __syncthreads();
    int idx = blockIdx.x * blockDim.x + threadIdx.x;
    if (idx >= N_ROWS * OUT_DIM) return;
    int c = idx & 1;
    out[idx] = g_logits[idx] * s_scale[c] + s_shift[c];
}

// ---------------- launch ----------------
extern "C" void kernel_launch(void* const* d_in, const int* in_sizes, int n_in,
                              void* d_out, int out_size) {
    const float* x     = (const float*)d_in[0];
    const float* W1    = (const float*)d_in[1];
    const float* b1    = (const float*)d_in[2];
    const float* W2    = (const float*)d_in[3];
    const float* b2    = (const float*)d_in[4];
    const float* W3    = (const float*)d_in[5];
    const float* b3    = (const float*)d_in[6];
    const float* gamma = (const float*)d_in[7];
    const float* beta  = (const float*)d_in[8];
    float* out = (float*)d_out;

    k_norm<<<N_ROWS / 8, 256>>>(x);
    k_gram<<<N_TILES, 256>>>(x);
    k_mlp<<<N_ROWS / 128, 128>>>(x, W1, b1, W2, b2, W3, b3);
    k_bn<<<(N_ROWS * OUT_DIM + 255) / 256, 256>>>(gamma, beta, out);
}

// round 6
// speedup vs baseline: 1.5169x; 1.1364x over previous
#include <cuda_runtime.h>
#include <cuda_bf16.h>
#include <cuda_fp8.h>
#include <cstdint>
#include <math.h>

#define N_ROWS 16384
#define F_DIM  128
#define H1_DIM 64
#define H2_DIM 32
#define OUT_DIM 2

#define TB      128                       // gram tile (square), K=64 head
#define NB      (N_ROWS / TB)             // 128
#define N_TILES (NB * (NB + 1) / 2)       // 8256

#define SCREEN_T 0.9186f                  // sqrt(0.9) - 0.03 fp8 margin
#define TILE_BYTES 8192                   // 128 rows x 64B head

// ---------------- device scratch ----------------
__device__ __align__(128) uint32_t g_x8[N_ROWS * 16];  // 1 MB: head rows pre-swizzled per 8KB tile
__device__ __align__(128) float    g_tail[N_ROWS];     // tail norm of normalized row
__device__ float    g_rnorm[N_ROWS];
__device__ float    g_neigh[N_ROWS * F_DIM];
__device__ int      g_deg[N_ROWS];
__device__ float    g_logits[N_ROWS * OUT_DIM];
__device__ double   g_sum[2];
__device__ double   g_sq[2];

__device__ __forceinline__ uint32_t smem_u32(const void* p) {
    uint32_t a;
    asm("{ .reg .u64 t; cvta.to.shared.u64 t, %1; cvt.u32.u64 %0, t; }" : "=r"(a) : "l"(p));
    return a;
}

// byte offset inside an 8KB tile: two 64B logical rows per 128B smem row, XOR swizzle.
// r: logical row 0..127, c: 16B chunk 0..3
__device__ __forceinline__ uint32_t pack_off(int r, int c) {
    int R = r >> 1;
    int u = ((r & 1) << 2) | c;
    return (uint32_t)(R * 128 + ((u ^ (R & 7)) << 4));
}

// triangular decode: linear tile t -> (ib, jb), jb >= ib
__device__ __forceinline__ void decode_tile(int t, int& ib, int& jb) {
    int u = N_TILES - 1 - t;
    int rb = (int)((sqrtf(8.0f * (float)u + 1.0f) - 1.0f) * 0.5f);
    while (rb * (rb + 1) / 2 > u) rb--;
    while ((rb + 1) * (rb + 2) / 2 <= u) rb++;
    ib = NB - 1 - rb;
    jb = NB - 1 - (u - rb * (rb + 1) / 2);
}

__device__ __forceinline__ void bulk_cp(uint32_t dst, const void* src, uint32_t bytes,
                                        uint32_t mbar) {
    asm volatile(
        "cp.async.bulk.shared::cta.global.mbarrier::complete_tx::bytes [%0], [%1], %2, [%3];"
        :: "r"(dst), "l"(src), "r"(bytes), "r"(mbar) : "memory");
}
__device__ __forceinline__ void mbar_init(uint32_t addr, uint32_t cnt) {
    asm volatile("mbarrier.init.shared.b64 [%0], %1;" :: "r"(addr), "r"(cnt) : "memory");
}
__device__ __forceinline__ void mbar_expect_tx(uint32_t addr, uint32_t tx) {
    asm volatile("mbarrier.arrive.expect_tx.shared.b64 _, [%0], %1;"
                 :: "r"(addr), "r"(tx) : "memory");
}
__device__ __forceinline__ void mbar_wait(uint32_t addr, uint32_t parity) {
    asm volatile(
        "{\n\t.reg .pred P;\n\t"
        "WAITLP_%=:\n\t"
        "mbarrier.try_wait.parity.acquire.cta.shared::cta.b64 P, [%0], %1, 0x989680;\n\t"
        "@P bra.uni WAITDN_%=;\n\t"
        "bra.uni WAITLP_%=;\n\t"
        "WAITDN_%=:\n\t}"
        :: "r"(addr), "r"(parity) : "memory");
}

// ---------------- kernel 1: norms, head->e4m3 (pre-swizzled), tail norms ----------------
__global__ void __launch_bounds__(256) k_norm(const float* __restrict__ x) {
    if (blockIdx.x == 0 && threadIdx.x == 0) {
        g_sum[0] = 0.0; g_sum[1] = 0.0; g_sq[0] = 0.0; g_sq[1] = 0.0;
    }
    int row = (blockIdx.x * blockDim.x + threadIdx.x) >> 5;
    int lane = threadIdx.x & 31;
    if (row >= N_ROWS) return;
    float4 v = reinterpret_cast<const float4*>(x)[(size_t)row * 32 + lane];
    float ss = v.x * v.x + v.y * v.y + v.z * v.z + v.w * v.w;
    float st = (lane >= 16) ? ss : 0.f;
#pragma unroll
    for (int o = 16; o > 0; o >>= 1) {
        ss += __shfl_xor_sync(0xffffffffu, ss, o);
        st += __shfl_xor_sync(0xffffffffu, st, o);
    }
    float inv = 1.0f / (sqrtf(ss) + 1e-12f);
    if (lane < 16) {   // head features -> fp8, stored in swizzled 8KB-tile layout
        __nv_fp8x2_storage_t p0 = __nv_cvt_float2_to_fp8x2(make_float2(v.x * inv, v.y * inv),
                                                           __NV_SATFINITE, __NV_E4M3);
        __nv_fp8x2_storage_t p1 = __nv_cvt_float2_to_fp8x2(make_float2(v.z * inv, v.w * inv),
                                                           __NV_SATFINITE, __NV_E4M3);
        uint32_t word = (uint32_t)p0 | ((uint32_t)p1 << 16);
        int t = row >> 7, rl = row & 127;
        int c16 = lane >> 2, w = lane & 3;
        g_x8[t * 2048 + (pack_off(rl, c16) >> 2) + w] = word;
    }
    if (lane == 0) {
        g_tail[row] = sqrtf(st) * inv;
        g_rnorm[row] = inv;
        g_deg[row] = 0;
    }
    reinterpret_cast<float4*>(g_neigh)[(size_t)row * 32 + lane] = make_float4(0.f, 0.f, 0.f, 0.f);
}

// ---------------- kernel 2: fp8 head-gram (bulk-copy loads) + screen + exact recheck ----------------
__global__ void __launch_bounds__(256, 2) k_gram(const float* __restrict__ x) {
    int ib, jb;
    decode_tile(blockIdx.x, ib, jb);
    bool diag = (ib == jb);

    __shared__ alignas(1024) char sA[TILE_BYTES];
    __shared__ alignas(1024) char sB[TILE_BYTES];
    __shared__ alignas(16) float stA[TB];
    __shared__ alignas(16) float stB[TB];
    __shared__ alignas(8) unsigned long long mbar_s;

    int tid = threadIdx.x;
    uint32_t sa = smem_u32(sA), sbm = smem_u32(sB);
    uint32_t mbar = smem_u32(&mbar_s);

    if (tid == 0) mbar_init(mbar, 1);
    __syncthreads();
    if (tid == 0) {
        uint32_t tx = diag ? (TILE_BYTES + 512) : (2 * TILE_BYTES + 1024);
        mbar_expect_tx(mbar, tx);
        bulk_cp(sa, g_x8 + (size_t)ib * 2048, TILE_BYTES, mbar);
        bulk_cp(smem_u32(stA), g_tail + ib * TB, 512, mbar);
        if (!diag) {
            bulk_cp(sbm, g_x8 + (size_t)jb * 2048, TILE_BYTES, mbar);
            bulk_cp(smem_u32(stB), g_tail + jb * TB, 512, mbar);
        }
    }
    mbar_wait(mbar, 0);

    uint32_t sb_use = diag ? sa : sbm;

    int wid = tid >> 5, lane = tid & 31;
    int m0 = (wid & 3) * 32;   // 4 warps along M
    int n0 = (wid >> 2) * 64;  // 2 warps along N

    float acc[2][8][4];
#pragma unroll
    for (int mi = 0; mi < 2; mi++)
#pragma unroll
        for (int nj = 0; nj < 8; nj++)
#pragma unroll
            for (int r = 0; r < 4; r++) acc[mi][nj][r] = 0.f;

    int q = lane >> 3, L = lane & 7;
    int rq = (q & 1) * 8 + L;
    int kq = q >> 1;

#pragma unroll
    for (int kk = 0; kk < 2; kk++) {           // 2 chunks of k=32 fp8 (head only)
        int cbase = kk * 2 + kq;
        uint32_t a[2][4];
#pragma unroll
        for (int mi = 0; mi < 2; mi++) {
            uint32_t addr = sa + pack_off(m0 + mi * 16 + rq, cbase);
            asm volatile("ldmatrix.sync.aligned.m8n8.x4.shared.b16 {%0,%1,%2,%3}, [%4];"
                         : "=r"(a[mi][0]), "=r"(a[mi][1]), "=r"(a[mi][2]), "=r"(a[mi][3])
                         : "r"(addr));
        }
        uint32_t b[8][2];
#pragma unroll
        for (int nq4 = 0; nq4 < 4; nq4++) {
            uint32_t r0, r1, r2, r3;
            uint32_t addr = sb_use + pack_off(n0 + nq4 * 16 + rq, cbase);
            asm volatile("ldmatrix.sync.aligned.m8n8.x4.shared.b16 {%0,%1,%2,%3}, [%4];"
                         : "=r"(r0), "=r"(r1), "=r"(r2), "=r"(r3)
                         : "r"(addr));
            b[nq4 * 2 + 0][0] = r0; b[nq4 * 2 + 0][1] = r2;
            b[nq4 * 2 + 1][0] = r1; b[nq4 * 2 + 1][1] = r3;
        }
#pragma unroll
        for (int mi = 0; mi < 2; mi++)
#pragma unroll
            for (int nj = 0; nj < 8; nj++)
                asm volatile(
                    "mma.sync.aligned.m16n8k32.row.col.f32.e4m3.e4m3.f32 "
                    "{%0,%1,%2,%3}, {%4,%5,%6,%7}, {%8,%9}, {%0,%1,%2,%3};"
                    : "+f"(acc[mi][nj][0]), "+f"(acc[mi][nj][1]),
                      "+f"(acc[mi][nj][2]), "+f"(acc[mi][nj][3])
                    : "r"(a[mi][0]), "r"(a[mi][1]), "r"(a[mi][2]), "r"(a[mi][3]),
                      "r"(b[nj][0]), "r"(b[nj][1]));
    }

    // ---- epilogue: coarse per-thread screen, then rare detailed pass ----
    int g = lane >> 2, tg = lane & 3;
    float ti[2][2];
#pragma unroll
    for (int mi = 0; mi < 2; mi++)
#pragma unroll
        for (int h = 0; h < 2; h++)
            ti[mi][h] = stA[m0 + mi * 16 + g + h * 8];
    float tj0[8], tj1[8];
    const float* stB_use = diag ? stA : stB;
#pragma unroll
    for (int nj = 0; nj < 8; nj++) {
        int j = n0 + nj * 8 + 2 * tg;
        tj0[nj] = stB_use[j];
        tj1[nj] = stB_use[j + 1];
    }

    float timax = fmaxf(fmaxf(ti[0][0], ti[0][1]), fmaxf(ti[1][0], ti[1][1]));
    float tjmax = 0.f;
#pragma unroll
    for (int nj = 0; nj < 8; nj++) tjmax = fmaxf(tjmax, fmaxf(tj0[nj], tj1[nj]));
    float amax = 0.f;
#pragma unroll
    for (int mi = 0; mi < 2; mi++)
#pragma unroll
        for (int nj = 0; nj < 8; nj++)
#pragma unroll
            for (int r = 0; r < 4; r++) amax = fmaxf(amax, fabsf(acc[mi][nj][r]));

    if (__any_sync(0xffffffffu, amax + timax * tjmax >= SCREEN_T)) {
        // detailed pass (rare): exact per-element bound + fp32 recheck
#pragma unroll
        for (int mi = 0; mi < 2; mi++) {
#pragma unroll
            for (int nj = 0; nj < 8; nj++) {
                float bnd[4];
                bnd[0] = fabsf(acc[mi][nj][0]) + ti[mi][0] * tj0[nj];
                bnd[1] = fabsf(acc[mi][nj][1]) + ti[mi][0] * tj1[nj];
                bnd[2] = fabsf(acc[mi][nj][2]) + ti[mi][1] * tj0[nj];
                bnd[3] = fabsf(acc[mi][nj][3]) + ti[mi][1] * tj1[nj];
                float bm = fmaxf(fmaxf(bnd[0], bnd[1]), fmaxf(bnd[2], bnd[3]));
                if (__any_sync(0xffffffffu, bm >= SCREEN_T)) {
#pragma unroll
                    for (int r = 0; r < 4; r++) {
                        if (bnd[r] >= SCREEN_T) {
                            int i = ib * TB + m0 + mi * 16 + g + (r >> 1) * 8;
                            int j = jb * TB + n0 + nj * 8 + 2 * tg + (r & 1);
                            if (i < j) {
                                const float4* xi = reinterpret_cast<const float4*>(x) + (size_t)i * 32;
                                const float4* xj = reinterpret_cast<const float4*>(x) + (size_t)j * 32;
                                float cdot = 0.f;
                                for (int f = 0; f < 32; f++) {
                                    float4 a4 = xi[f], b4 = xj[f];
                                    cdot += a4.x * b4.x + a4.y * b4.y + a4.z * b4.z + a4.w * b4.w;
                                }
                                cdot *= g_rnorm[i] * g_rnorm[j];
                                if (cdot * cdot >= 0.9f) {
                                    atomicAdd(&g_deg[i], 1);
                                    atomicAdd(&g_deg[j], 1);
                                    const float* xif = x + (size_t)i * F_DIM;
                                    const float* xjf = x + (size_t)j * F_DIM;
                                    float* ni = g_neigh + (size_t)i * F_DIM;
                                    float* njp = g_neigh + (size_t)j * F_DIM;
                                    for (int f = 0; f < F_DIM; f++) {
                                        atomicAdd(&ni[f], xjf[f]);
                                        atomicAdd(&njp[f], xif[f]);
                                    }
                                }
                            }
                        }
                    }
                }
            }
        }
    }
}

// ---------------- kernel 3: aggregation + MLP + BN statistics ----------------
__global__ void __launch_bounds__(128) k_mlp(const float* __restrict__ x,
                                             const float* __restrict__ W1, const float* __restrict__ b1,
                                             const float* __restrict__ W2, const float* __restrict__ b2,
                                             const float* __restrict__ W3, const float* __restrict__ b3) {
    __shared__ float sW1[F_DIM * H1_DIM];
    __shared__ float sW2[H1_DIM * H2_DIM];
    __shared__ float sW3[H2_DIM * OUT_DIM];
    __shared__ float sb1[H1_DIM], sb2[H2_DIM], sb3[OUT_DIM];
    __shared__ double swarp[4 * 4];

    int tid = threadIdx.x;
    for (int i = tid; i < F_DIM * H1_DIM; i += 128) sW1[i] = W1[i];
    for (int i = tid; i < H1_DIM * H2_DIM; i += 128) sW2[i] = W2[i];
    if (tid < H2_DIM * OUT_DIM) sW3[tid] = W3[tid];
    if (tid < H1_DIM) sb1[tid] = b1[tid];
    if (tid < H2_DIM) sb2[tid] = b2[tid];
    if (tid < OUT_DIM) sb3[tid] = b3[tid];
    __syncthreads();

    int row = blockIdx.x * 128 + tid;
    const float* xr = x + (size_t)row * F_DIM;
    const float* nr = g_neigh + (size_t)row * F_DIM;
    int d = g_deg[row];
    float invd = d > 0 ? 1.0f / (float)d : 0.f;

    float h1[H1_DIM];
#pragma unroll
    for (int k = 0; k < H1_DIM; k++) h1[k] = sb1[k];
    for (int f = 0; f < F_DIM; f++) {
        float a = (d > 0) ? 0.5f * (xr[f] + nr[f] * invd) : xr[f];
#pragma unroll
        for (int k = 0; k < H1_DIM; k++) h1[k] += a * sW1[f * H1_DIM + k];
    }
    float h2[H2_DIM];
#pragma unroll
    for (int m = 0; m < H2_DIM; m++) h2[m] = sb2[m];
#pragma unroll
    for (int k = 0; k < H1_DIM; k++) {
        float hk = fmaxf(h1[k], 0.f);
#pragma unroll
        for (int m = 0; m < H2_DIM; m++) h2[m] += hk * sW2[k * H2_DIM + m];
    }
    float l0 = sb3[0], l1 = sb3[1];
#pragma unroll
    for (int m = 0; m < H2_DIM; m++) {
        float hm = fmaxf(h2[m], 0.f);
        l0 += hm * sW3[m * 2 + 0];
        l1 += hm * sW3[m * 2 + 1];
    }
    g_logits[row * 2 + 0] = l0;
    g_logits[row * 2 + 1] = l1;

    double v[4] = { (double)l0, (double)l1, (double)l0 * l0, (double)l1 * l1 };
    int lane = tid & 31, wid = tid >> 5;
#pragma unroll
    for (int s = 0; s < 4; s++) {
        double t = v[s];
#pragma unroll
        for (int o = 16; o > 0; o >>= 1) t += __shfl_xor_sync(0xffffffffu, t, o);
        if (lane == 0) swarp[wid * 4 + s] = t;
    }
    __syncthreads();
    if (tid < 4) {
        double s = 0.0;
#pragma unroll
        for (int w = 0; w < 4; w++) s += swarp[w * 4 + tid];
        if (tid < 2) atomicAdd(&g_sum[tid], s);
        else         atomicAdd(&g_sq[tid - 2], s);
    }
}

// ---------------- kernel 4: batch-norm normalize (float4) ----------------
__global__ void __launch_bounds__(256) k_bn(const float* __restrict__ gamma,
                                            const float* __restrict__ beta,
                                            float* __restrict__ out) {
    __shared__ float s_scale[2], s_shift[2];
    if (threadIdx.x < 2) {
        int c = threadIdx.x;
        double n = (double)N_ROWS;
        double mu = g_sum[c] / n;
        double var = g_sq[c] / n - mu * mu;
        double inv = 1.0 / sqrt(var + 1e-5);
        float g = gamma[c];
        s_scale[c] = (float)inv * g;
        s_shift[c] = beta[c] - (float)(mu * inv) * g;
    }
    __syncthreads();
    int idx = blockIdx.x * blockDim.x + threadIdx.x;   // one float4 = 2 (row, 2ch) pairs
    float4 v = reinterpret_cast<const float4*>(g_logits)[idx];
    float4 o;
    o.x = v.x * s_scale[0] + s_shift[0];
    o.y = v.y * s_scale[1] + s_shift[1];
    o.z = v.z * s_scale[0] + s_shift[0];
    o.w = v.w * s_scale[1] + s_shift[1];
    reinterpret_cast<float4*>(out)[idx] = o;
}

// ---------------- launch ----------------
extern "C" void kernel_launch(void* const* d_in, const int* in_sizes, int n_in,
                              void* d_out, int out_size) {
    const float* x     = (const float*)d_in[0];
    const float* W1    = (const float*)d_in[1];
    const float* b1    = (const float*)d_in[2];
    const float* W2    = (const float*)d_in[3];
    const float* b2    = (const float*)d_in[4];
    const float* W3    = (const float*)d_in[5];
    const float* b3    = (const float*)d_in[6];
    const float* gamma = (const float*)d_in[7];
    const float* beta  = (const float*)d_in[8];
    float* out = (float*)d_out;

    k_norm<<<N_ROWS / 8, 256>>>(x);
    k_gram<<<N_TILES, 256>>>(x);
    k_mlp<<<N_ROWS / 128, 128>>>(x, W1, b1, W2, b2, W3, b3);
    k_bn<<<(N_ROWS * OUT_DIM / 4) / 256, 256>>>(gamma, beta, out);
}